// round 3
// baseline (speedup 1.0000x reference)
#include <cuda_runtime.h>

#define SEQ   8192
#define DIM   2048
#define H     16
#define DH    128
#define PDIM  512
#define EPSF  1e-5f
#define NCHUNK 128
#define CHS   (SEQ / NCHUNK)      // 64 rows per chunk
#define NJC   16                  // j-chunks of 128 cols in k1

typedef unsigned long long ull;

// ---------------- scratch (device globals) ----------------------------------
__device__ __align__(16) ull   g_Wqp[DIM * 8];           // packed head-pairs, [j][hp]
__device__ __align__(16) float g_lp[NJC * H * SEQ];      // partial logits [jc][h][s]
__device__ __align__(16) float g_attn[H * SEQ];          // softmax weights
__device__ __align__(16) float g_ypart[NCHUNK][H * DIM]; // partial y sums
__device__ __align__(16) float g_y[H * DIM];
__device__ __align__(16) float g_x1[DIM];
__device__ float                g_h1[PDIM];
__device__ __align__(16) float g_r[PDIM];
__device__ __align__(16) float g_add[DIM];

// ---------------- packed f32x2 helpers ---------------------------------------
__device__ __forceinline__ ull splat2(float a) {
    ull r; asm("mov.b64 %0, {%1, %1};" : "=l"(r) : "f"(a)); return r;
}
__device__ __forceinline__ ull pack2(float lo, float hi) {
    ull r; asm("mov.b64 %0, {%1, %2};" : "=l"(r) : "f"(lo), "f"(hi)); return r;
}
__device__ __forceinline__ void unpack2(ull v, float& lo, float& hi) {
    asm("mov.b64 {%0, %1}, %2;" : "=f"(lo), "=f"(hi) : "l"(v));
}
__device__ __forceinline__ void ffma2(ull& d, ull a, ull b) {
    asm("fma.rn.f32x2 %0, %1, %2, %0;" : "+l"(d) : "l"(a), "l"(b));
}

// ---- k0: Wqp[j][hp] = pack( q_h . W_k[h-block, :, j] for h=2hp, 2hp+1 ) ----
__global__ void k0_wq(const float* __restrict__ q,
                      const float* __restrict__ Wkv) {
    int idx = blockIdx.x * 256 + threadIdx.x;    // 16384 threads
    int hp = idx >> 11, j = idx & (DIM - 1);
    int h0 = 2 * hp, h1 = 2 * hp + 1;
    const float* w0 = Wkv + (size_t)h0 * DH * DIM + j;
    const float* w1 = Wkv + (size_t)h1 * DH * DIM + j;
    const float* q0 = q + h0 * DH;
    const float* q1 = q + h1 * DH;
    float a0 = 0.f, a1 = 0.f;
    #pragma unroll 8
    for (int d = 0; d < DH; ++d) {
        a0 += q0[d] * w0[(size_t)d * DIM];
        a1 += q1[d] * w1[(size_t)d * DIM];
    }
    g_Wqp[(size_t)j * 8 + hp] = pack2(a0, a1);
}

// ---- k1: partial logits per (row, j-chunk) ----------------------------------
// Warp owns a 128-col j-slice; Wq pairs cached in regs; 32 rows per warp.
// Reduction: recursive halving. After steps o=16,8,4,2 each lane holds one
// value; final shfl_xor(1) completes. head = (lane>>1)&15, even lanes write.
__global__ void __launch_bounds__(256) k1_logits(const float* __restrict__ x) {
    int gw = blockIdx.x * 8 + (threadIdx.x >> 5);   // 4096 warps
    int lane = threadIdx.x & 31;
    int rc = gw >> 4;          // 256 row chunks of 32
    int jc = gw & 15;          // 16 j-chunks of 128 cols
    int j0 = jc * 128 + lane * 4;

    ull wq2[4][8];
    #pragma unroll
    for (int jj = 0; jj < 4; ++jj)
        #pragma unroll
        for (int hp = 0; hp < 8; ++hp)
            wq2[jj][hp] = g_Wqp[(size_t)(j0 + jj) * 8 + hp];

    int head = (lane >> 1) & 15;
    bool writer = !(lane & 1);
    float* lpout = g_lp + (size_t)(jc * H + head) * SEQ;

    for (int r = 0; r < 32; ++r) {
        int row = rc * 32 + r;
        float4 x4 = *(const float4*)(x + (size_t)row * DIM + j0);
        ull p2[8];
        #pragma unroll
        for (int hp = 0; hp < 8; ++hp) p2[hp] = 0ull;
        ull s0 = splat2(x4.x), s1 = splat2(x4.y), s2 = splat2(x4.z), s3 = splat2(x4.w);
        #pragma unroll
        for (int hp = 0; hp < 8; ++hp) {
            ffma2(p2[hp], s0, wq2[0][hp]);
            ffma2(p2[hp], s1, wq2[1][hp]);
            ffma2(p2[hp], s2, wq2[2][hp]);
            ffma2(p2[hp], s3, wq2[3][hp]);
        }
        float v[16];
        #pragma unroll
        for (int hp = 0; hp < 8; ++hp) unpack2(p2[hp], v[2 * hp], v[2 * hp + 1]);

        // step o=16: 16 -> 8 values
        float a8[8];
        #pragma unroll
        for (int i = 0; i < 8; ++i) {
            float lo = v[i]     + __shfl_xor_sync(0xffffffffu, v[i],     16);
            float hi = v[i + 8] + __shfl_xor_sync(0xffffffffu, v[i + 8], 16);
            a8[i] = (lane & 16) ? hi : lo;
        }
        // step o=8: 8 -> 4
        float a4[4];
        #pragma unroll
        for (int i = 0; i < 4; ++i) {
            float lo = a8[i]     + __shfl_xor_sync(0xffffffffu, a8[i],     8);
            float hi = a8[i + 4] + __shfl_xor_sync(0xffffffffu, a8[i + 4], 8);
            a4[i] = (lane & 8) ? hi : lo;
        }
        // step o=4: 4 -> 2
        float a2[2];
        #pragma unroll
        for (int i = 0; i < 2; ++i) {
            float lo = a4[i]     + __shfl_xor_sync(0xffffffffu, a4[i],     4);
            float hi = a4[i + 2] + __shfl_xor_sync(0xffffffffu, a4[i + 2], 4);
            a2[i] = (lane & 4) ? hi : lo;
        }
        // step o=2: 2 -> 1
        float lo1 = a2[0] + __shfl_xor_sync(0xffffffffu, a2[0], 2);
        float hi1 = a2[1] + __shfl_xor_sync(0xffffffffu, a2[1], 2);
        float a1v = (lane & 2) ? hi1 : lo1;
        // final o=1: sum lane pairs
        a1v += __shfl_xor_sync(0xffffffffu, a1v, 1);
        if (writer) lpout[row] = a1v;
    }
}

// ---- k2: reduce j-chunk partials + softmax; one block per head --------------
__global__ void __launch_bounds__(1024) k2_softmax() {
    int h = blockIdx.x, tid = threadIdx.x;
    __shared__ float red[1024];
    const float scale = 0.08838834764831845f;    // 1/sqrt(128)
    float* row = g_attn + (size_t)h * SEQ;
    float m = -1e30f;
    for (int s = tid; s < SEQ; s += 1024) {
        float v = 0.f;
        #pragma unroll
        for (int jc = 0; jc < NJC; ++jc)
            v += g_lp[(size_t)(jc * H + h) * SEQ + s];
        v *= scale;
        row[s] = v;
        m = fmaxf(m, v);
    }
    red[tid] = m; __syncthreads();
    for (int o = 512; o > 0; o >>= 1) {
        if (tid < o) red[tid] = fmaxf(red[tid], red[tid + o]);
        __syncthreads();
    }
    m = red[0]; __syncthreads();
    float sum = 0.f;
    for (int s = tid; s < SEQ; s += 1024) {
        float e = __expf(row[s] - m);
        row[s] = e;
        sum += e;
    }
    red[tid] = sum; __syncthreads();
    for (int o = 512; o > 0; o >>= 1) {
        if (tid < o) red[tid] += red[tid + o];
        __syncthreads();
    }
    float inv = 1.f / red[0];
    __syncthreads();
    for (int s = tid; s < SEQ; s += 1024) row[s] *= inv;
}

// ---- k3: partial y over s-chunk; head-pair-packed f32x2 accumulators --------
// Block = (chunk, col-half). Thread owns 2 adjacent columns, all 16 heads.
__global__ void __launch_bounds__(512) k3_yaccum(const float* __restrict__ x) {
    int c = blockIdx.x >> 1;
    int half = blockIdx.x & 1;
    int tid = threadIdx.x;
    int col0 = half * 1024 + 2 * tid;
    __shared__ ull sat2[CHS * 8];                // packed attn head-pairs
    {
        int i = tid;                             // CHS*8 = 512 entries
        int sl = i >> 3, hp = i & 7;
        int s = c * CHS + sl;
        sat2[i] = pack2(g_attn[(size_t)(2 * hp) * SEQ + s],
                        g_attn[(size_t)(2 * hp + 1) * SEQ + s]);
    }
    __syncthreads();
    ull acc_a[8], acc_b[8];                      // col0 / col0+1, 8 head-pairs each
    #pragma unroll
    for (int hp = 0; hp < 8; ++hp) { acc_a[hp] = 0ull; acc_b[hp] = 0ull; }
    int base = c * CHS;
    for (int sl = 0; sl < CHS; ++sl) {
        float2 xv = *(const float2*)(x + (size_t)(base + sl) * DIM + col0);
        ull sa = splat2(xv.x), sb = splat2(xv.y);
        #pragma unroll
        for (int hp = 0; hp < 8; ++hp) {
            ull b2 = sat2[sl * 8 + hp];
            ffma2(acc_a[hp], sa, b2);
            ffma2(acc_b[hp], sb, b2);
        }
    }
    float* yp = g_ypart[c];
    #pragma unroll
    for (int hp = 0; hp < 8; ++hp) {
        float a0, a1, b0, b1;
        unpack2(acc_a[hp], a0, a1);
        unpack2(acc_b[hp], b0, b1);
        *(float2*)(yp + (size_t)(2 * hp) * DIM + col0)     = make_float2(a0, b0);
        *(float2*)(yp + (size_t)(2 * hp + 1) * DIM + col0) = make_float2(a1, b1);
    }
}

// ---- k3b: reduce partials -> g_y --------------------------------------------
__global__ void k3b_reduce() {
    int i = blockIdx.x * 256 + threadIdx.x;      // 32768 threads
    float s = 0.f;
    for (int c = 0; c < NCHUNK; ++c) s += g_ypart[c][i];
    g_y[i] = s;
}

// ---- k4: x1[i] = W_v[i,:] . y[h(i),:] + b_v[i]; one warp per output ---------
__global__ void k4_x1(const float* __restrict__ Wkv, const float* __restrict__ bkv) {
    int warp = (blockIdx.x * 256 + threadIdx.x) >> 5;  // 2048 warps
    int lane = threadIdx.x & 31;
    int h = warp >> 7;
    const float4* w = (const float4*)(Wkv + (size_t)(DIM + warp) * DIM);
    const float4* y = (const float4*)(g_y + (size_t)h * DIM);
    float a = 0.f;
    for (int it = lane; it < DIM / 4; it += 32) {
        float4 wv = w[it], yv = y[it];
        a += wv.x * yv.x + wv.y * yv.y + wv.z * yv.z + wv.w * yv.w;
    }
    #pragma unroll
    for (int o = 16; o > 0; o >>= 1) a += __shfl_xor_sync(0xffffffffu, a, o);
    if (lane == 0) g_x1[warp] = a + bkv[DIM + warp];
}

// ---- k5: h1 = W_p1 @ x1 + b_p1 ----------------------------------------------
__global__ void k5_p1(const float* __restrict__ Wp1, const float* __restrict__ bp1) {
    int warp = (blockIdx.x * 256 + threadIdx.x) >> 5;  // 512 warps
    int lane = threadIdx.x & 31;
    const float4* w = (const float4*)(Wp1 + (size_t)warp * DIM);
    const float4* v = (const float4*)g_x1;
    float a = 0.f;
    for (int it = lane; it < DIM / 4; it += 32) {
        float4 wv = w[it], vv = v[it];
        a += wv.x * vv.x + wv.y * vv.y + wv.z * vv.z + wv.w * vv.w;
    }
    #pragma unroll
    for (int o = 16; o > 0; o >>= 1) a += __shfl_xor_sync(0xffffffffu, a, o);
    if (lane == 0) g_h1[warp] = a + bp1[warp];
}

// ---- k6: LayerNorm(512) + relu ----------------------------------------------
__global__ void k6_ln(const float* __restrict__ lnw, const float* __restrict__ lnb) {
    __shared__ float red[PDIM];
    int tid = threadIdx.x;
    float v = g_h1[tid];
    red[tid] = v; __syncthreads();
    for (int o = 256; o > 0; o >>= 1) {
        if (tid < o) red[tid] += red[tid + o];
        __syncthreads();
    }
    float mu = red[0] * (1.f / PDIM); __syncthreads();
    float d = v - mu;
    red[tid] = d * d; __syncthreads();
    for (int o = 256; o > 0; o >>= 1) {
        if (tid < o) red[tid] += red[tid + o];
        __syncthreads();
    }
    float var = red[0] * (1.f / PDIM);
    float n = d * rsqrtf(var + EPSF) * lnw[tid] + lnb[tid];
    g_r[tid] = fmaxf(n, 0.f);
}

// ---- k7: add = W_p2 @ r + b_p2 ----------------------------------------------
__global__ void k7_p2(const float* __restrict__ Wp2, const float* __restrict__ bp2) {
    int warp = (blockIdx.x * 256 + threadIdx.x) >> 5;  // 2048 warps
    int lane = threadIdx.x & 31;
    const float4* w = (const float4*)(Wp2 + (size_t)warp * PDIM);
    const float4* v = (const float4*)g_r;
    float a = 0.f;
    for (int it = lane; it < PDIM / 4; it += 32) {
        float4 wv = w[it], vv = v[it];
        a += wv.x * vv.x + wv.y * vv.y + wv.z * vv.z + wv.w * vv.w;
    }
    #pragma unroll
    for (int o = 16; o > 0; o >>= 1) a += __shfl_xor_sync(0xffffffffu, a, o);
    if (lane == 0) g_add[warp] = a + bp2[warp];
}

// ---- k8: out = x + broadcast(add) -------------------------------------------
__global__ void __launch_bounds__(256) k8_resid(const float* __restrict__ x,
                                                float* __restrict__ out) {
    size_t i = (size_t)blockIdx.x * 256 + threadIdx.x;
    const float4* x4 = (const float4*)x;
    const float4* a4 = (const float4*)g_add;
    float4 xv = x4[i];
    float4 av = a4[i & (DIM / 4 - 1)];
    float4 o;
    o.x = xv.x + av.x; o.y = xv.y + av.y; o.z = xv.z + av.z; o.w = xv.w + av.w;
    ((float4*)out)[i] = o;
}

extern "C" void kernel_launch(void* const* d_in, const int* in_sizes, int n_in,
                              void* d_out, int out_size) {
    const float* x    = (const float*)d_in[0];
    const float* q    = (const float*)d_in[1];
    const float* Wkv  = (const float*)d_in[2];
    const float* bkv  = (const float*)d_in[3];
    const float* Wp1  = (const float*)d_in[4];
    const float* bp1  = (const float*)d_in[5];
    const float* Wp2  = (const float*)d_in[6];
    const float* bp2  = (const float*)d_in[7];
    const float* lnw  = (const float*)d_in[8];
    const float* lnb  = (const float*)d_in[9];
    float* out = (float*)d_out;

    k0_wq<<<64, 256>>>(q, Wkv);
    k1_logits<<<512, 256>>>(x);
    k2_softmax<<<H, 1024>>>();
    k3_yaccum<<<NCHUNK * 2, 512>>>(x);
    k3b_reduce<<<(H * DIM) / 256, 256>>>();
    k4_x1<<<DIM / 8, 256>>>(Wkv, bkv);
    k5_p1<<<PDIM / 8, 256>>>(Wp1, bp1);
    k6_ln<<<1, PDIM>>>(lnw, lnb);
    k7_p2<<<DIM / 8, 256>>>(Wp2, bp2);
    k8_resid<<<(SEQ * DIM / 4) / 256, 256>>>(x, out);
}

// round 4
// speedup vs baseline: 1.2579x; 1.2579x over previous
#include <cuda_runtime.h>

#define SEQ   8192
#define DIM   2048
#define H     16
#define DH    128
#define PDIM  512
#define EPSF  1e-5f
#define NCH3  64
#define CH3   (SEQ / NCH3)        // 128 rows per k3 chunk
#define K1_BLOCKS 128
#define K1_ROWS   64
#define LSCALE 0.08838834764831845f   // 1/sqrt(128)

typedef unsigned long long ull;

// ---------------- scratch (device globals) ----------------------------------
__device__ __align__(16) ull   g_Wqp[DIM * 8];            // [j][hp] packed head-pairs
__device__ __align__(16) float g_attn[H * SEQ];           // UNNORMALIZED exp weights
__device__ __align__(16) float g_psum[K1_BLOCKS * H];     // per-block per-head exp sums
__device__ __align__(16) float g_ypart[NCH3][H * DIM];    // partial y sums
__device__ __align__(16) float g_y[H * DIM];              // normalized y
__device__ __align__(16) float g_x1[DIM];
__device__ __align__(16) float g_h1[PDIM];
__device__ __align__(16) float g_add[DIM];

// ---------------- packed f32x2 helpers ---------------------------------------
__device__ __forceinline__ ull splat2(float a) {
    ull r; asm("mov.b64 %0, {%1, %1};" : "=l"(r) : "f"(a)); return r;
}
__device__ __forceinline__ ull pack2(float lo, float hi) {
    ull r; asm("mov.b64 %0, {%1, %2};" : "=l"(r) : "f"(lo), "f"(hi)); return r;
}
__device__ __forceinline__ void unpack2(ull v, float& lo, float& hi) {
    asm("mov.b64 {%0, %1}, %2;" : "=f"(lo), "=f"(hi) : "l"(v));
}
__device__ __forceinline__ void ffma2(ull& d, ull a, ull b) {
    asm("fma.rn.f32x2 %0, %1, %2, %0;" : "+l"(d) : "l"(a), "l"(b));
}

// ---- k0: Wqp[j][hp] = pack( q_h . W_k[h,:,j] for h=2hp, 2hp+1 ) -------------
__global__ void k0_wq(const float* __restrict__ q,
                      const float* __restrict__ Wkv) {
    int idx = blockIdx.x * 256 + threadIdx.x;    // 16384 threads
    int hp = idx >> 11, j = idx & (DIM - 1);
    int h0 = 2 * hp, h1 = 2 * hp + 1;
    const float* w0 = Wkv + (size_t)h0 * DH * DIM + j;
    const float* w1 = Wkv + (size_t)h1 * DH * DIM + j;
    const float* q0 = q + h0 * DH;
    const float* q1 = q + h1 * DH;
    float a0 = 0.f, a1 = 0.f;
    #pragma unroll 8
    for (int d = 0; d < DH; ++d) {
        a0 += q0[d] * w0[(size_t)d * DIM];
        a1 += q1[d] * w1[(size_t)d * DIM];
    }
    g_Wqp[(size_t)j * 8 + hp] = pack2(a0, a1);
}

// ---- k1: exp-logits + per-block head sums -----------------------------------
// Block: 64 rows x all 2048 j. 8 warps, each a 256-j slice, lane owns rows
// (lane, lane+32), 16 head accumulators as 8 f32x2. No shuffles in hot loop.
// smem: Wq 128KB | x stage 8x(64x18)f | partials 8x(64x20)f  = 204 KB dynamic.
__global__ void __launch_bounds__(256) k1_logits(const float* __restrict__ x) {
    extern __shared__ __align__(16) unsigned char smem[];
    ull*   wq_s = (ull*)smem;                         // [2048][8]
    float* xsb  = (float*)(smem + 131072);            // 8 x [64][18]
    float* part = (float*)(smem + 167936);            // 8 x [64][20]
    __shared__ float wsum[8][16];

    int tid = threadIdx.x, lane = tid & 31, wid = tid >> 5;
    int rowbase = blockIdx.x * K1_ROWS;

    // stage Wq (128 KB) cooperatively
    {
        const float4* src = (const float4*)g_Wqp;     // 8192 float4
        float4* dst = (float4*)wq_s;
        for (int i = tid; i < 8192; i += 256) dst[i] = src[i];
    }
    __syncthreads();

    float* xw = xsb + wid * (64 * 18);
    ull accA[8], accB[8];
    #pragma unroll
    for (int hp = 0; hp < 8; ++hp) { accA[hp] = 0ull; accB[hp] = 0ull; }
    int jslice = wid * 256;

    for (int ch = 0; ch < 16; ++ch) {
        int j0 = jslice + ch * 16;
        // stage x[rowbase..+63][j0..j0+15] (warp-private, stride 18)
        #pragma unroll
        for (int t = 0; t < 8; ++t) {
            int id = t * 32 + lane;
            int r = id >> 2, c4 = id & 3;
            float4 v = *(const float4*)(x + (size_t)(rowbase + r) * DIM + j0 + c4 * 4);
            float* p = xw + r * 18 + c4 * 4;
            p[0] = v.x; p[1] = v.y; p[2] = v.z; p[3] = v.w;
        }
        __syncwarp();
        #pragma unroll
        for (int jp = 0; jp < 8; ++jp) {
            int j = j0 + jp * 2;
            const ulonglong2* wp = (const ulonglong2*)(wq_s + (size_t)j * 8);
            ulonglong2 a0 = wp[0], a1 = wp[1], a2 = wp[2], a3 = wp[3];  // j
            ulonglong2 b0 = wp[4], b1 = wp[5], b2 = wp[6], b3 = wp[7];  // j+1
            ull w0[8] = {a0.x, a0.y, a1.x, a1.y, a2.x, a2.y, a3.x, a3.y};
            ull w1[8] = {b0.x, b0.y, b1.x, b1.y, b2.x, b2.y, b3.x, b3.y};
            float2 xa = *(const float2*)(xw + lane * 18 + jp * 2);
            float2 xb = *(const float2*)(xw + (lane + 32) * 18 + jp * 2);
            ull sax = splat2(xa.x), say = splat2(xa.y);
            ull sbx = splat2(xb.x), sby = splat2(xb.y);
            #pragma unroll
            for (int hp = 0; hp < 8; ++hp) {
                ffma2(accA[hp], sax, w0[hp]);
                ffma2(accA[hp], say, w1[hp]);
                ffma2(accB[hp], sbx, w0[hp]);
                ffma2(accB[hp], sby, w1[hp]);
            }
        }
        __syncwarp();
    }

    // write per-warp partials [w][r][h] (stride 20, conflict-free STS.128)
    float* pw = part + wid * (64 * 20);
    {
        float fa[16], fb[16];
        #pragma unroll
        for (int hp = 0; hp < 8; ++hp) {
            unpack2(accA[hp], fa[2 * hp], fa[2 * hp + 1]);
            unpack2(accB[hp], fb[2 * hp], fb[2 * hp + 1]);
        }
        #pragma unroll
        for (int k = 0; k < 4; ++k) {
            *(float4*)(pw + lane * 20 + 4 * k) =
                make_float4(fa[4 * k], fa[4 * k + 1], fa[4 * k + 2], fa[4 * k + 3]);
            *(float4*)(pw + (lane + 32) * 20 + 4 * k) =
                make_float4(fb[4 * k], fb[4 * k + 1], fb[4 * k + 2], fb[4 * k + 3]);
        }
    }
    __syncthreads();

    // combine 8 warp-partials, exp, write attn + head sums
    int h = tid & 15, g = tid >> 4;                   // 16 heads x 16 row-groups
    float hsum = 0.f, ev[4];
    #pragma unroll
    for (int k = 0; k < 4; ++k) {
        int r = g * 4 + k;
        float s = 0.f;
        #pragma unroll
        for (int w = 0; w < 8; ++w) s += part[w * 1280 + r * 20 + h];
        float e = __expf(s * LSCALE);
        ev[k] = e; hsum += e;
    }
    *(float4*)(g_attn + (size_t)h * SEQ + rowbase + g * 4) =
        make_float4(ev[0], ev[1], ev[2], ev[3]);
    hsum += __shfl_xor_sync(0xffffffffu, hsum, 16);
    if (lane < 16) wsum[wid][h] = hsum;
    __syncthreads();
    if (tid < 16) {
        float s = 0.f;
        #pragma unroll
        for (int w = 0; w < 8; ++w) s += wsum[w][tid];
        g_psum[blockIdx.x * 16 + tid] = s;
    }
}

// ---- k3: partial y over s-chunk; 2 cols x 8 head-pair f32x2 accs ------------
__global__ void __launch_bounds__(256) k3_yaccum(const float* __restrict__ x) {
    int c = blockIdx.x >> 2;               // 64 chunks
    int qq = blockIdx.x & 3;               // col quarter
    int tid = threadIdx.x;
    int col0 = qq * 512 + 2 * tid;
    __shared__ ull sat2[CH3 * 8];          // 8 KB, packed attn head-pairs
    int s0 = c * CH3;
    for (int i = tid; i < CH3 * 8; i += 256) {
        int sl = i >> 3, hp = i & 7;
        sat2[i] = pack2(g_attn[(size_t)(2 * hp) * SEQ + s0 + sl],
                        g_attn[(size_t)(2 * hp + 1) * SEQ + s0 + sl]);
    }
    __syncthreads();
    ull aa[8], ab[8];
    #pragma unroll
    for (int hp = 0; hp < 8; ++hp) { aa[hp] = 0ull; ab[hp] = 0ull; }
    for (int sl = 0; sl < CH3; ++sl) {
        float2 xv = *(const float2*)(x + (size_t)(s0 + sl) * DIM + col0);
        ull sa = splat2(xv.x), sb = splat2(xv.y);
        const ulonglong2* sp = (const ulonglong2*)(sat2 + sl * 8);
        ulonglong2 p0 = sp[0], p1 = sp[1], p2 = sp[2], p3 = sp[3];
        ffma2(aa[0], sa, p0.x); ffma2(ab[0], sb, p0.x);
        ffma2(aa[1], sa, p0.y); ffma2(ab[1], sb, p0.y);
        ffma2(aa[2], sa, p1.x); ffma2(ab[2], sb, p1.x);
        ffma2(aa[3], sa, p1.y); ffma2(ab[3], sb, p1.y);
        ffma2(aa[4], sa, p2.x); ffma2(ab[4], sb, p2.x);
        ffma2(aa[5], sa, p2.y); ffma2(ab[5], sb, p2.y);
        ffma2(aa[6], sa, p3.x); ffma2(ab[6], sb, p3.x);
        ffma2(aa[7], sa, p3.y); ffma2(ab[7], sb, p3.y);
    }
    float* yp = g_ypart[c];
    #pragma unroll
    for (int hp = 0; hp < 8; ++hp) {
        float l0, h0, l1, h1;
        unpack2(aa[hp], l0, h0);           // col0: heads 2hp, 2hp+1
        unpack2(ab[hp], l1, h1);           // col0+1
        *(float2*)(yp + (size_t)(2 * hp) * DIM + col0)     = make_float2(l0, l1);
        *(float2*)(yp + (size_t)(2 * hp + 1) * DIM + col0) = make_float2(h0, h1);
    }
}

// ---- k3b: reduce partials, normalize by head sums -> g_y --------------------
__global__ void __launch_bounds__(256) k3b_reduce() {
    __shared__ float partr[16][16];
    __shared__ float inv[16];
    int tid = threadIdx.x;
    {   // reduce g_psum[128][16] deterministically
        int h = tid & 15, g = tid >> 4;
        float s = 0.f;
        #pragma unroll
        for (int b = 0; b < 8; ++b) s += g_psum[(g * 8 + b) * 16 + h];
        partr[g][h] = s;
    }
    __syncthreads();
    if (tid < 16) {
        float s = 0.f;
        #pragma unroll
        for (int g = 0; g < 16; ++g) s += partr[g][tid];
        inv[tid] = 1.f / s;
    }
    __syncthreads();
    int i = blockIdx.x * 256 + tid;        // 32768 outputs
    float s = 0.f;
    for (int c = 0; c < NCH3; ++c) s += g_ypart[c][i];
    g_y[i] = s * inv[(i >> 11) & 15];
}

// ---- k4: x1[i] = W_v[i,:] . y[h(i),:] + b_v[i] ------------------------------
__global__ void __launch_bounds__(256) k4_x1(const float* __restrict__ Wkv,
                                             const float* __restrict__ bkv) {
    int warp = (blockIdx.x * 256 + threadIdx.x) >> 5;  // 2048 warps
    int lane = threadIdx.x & 31;
    int h = warp >> 7;
    const float4* w = (const float4*)(Wkv + (size_t)(DIM + warp) * DIM);
    const float4* y = (const float4*)(g_y + (size_t)h * DIM);
    float a = 0.f;
    for (int it = lane; it < DIM / 4; it += 32) {
        float4 wv = w[it], yv = y[it];
        a += wv.x * yv.x + wv.y * yv.y + wv.z * yv.z + wv.w * yv.w;
    }
    #pragma unroll
    for (int o = 16; o > 0; o >>= 1) a += __shfl_xor_sync(0xffffffffu, a, o);
    if (lane == 0) g_x1[warp] = a + bkv[DIM + warp];
}

// ---- k5: h1 = W_p1 @ x1 + b_p1 ----------------------------------------------
__global__ void __launch_bounds__(256) k5_p1(const float* __restrict__ Wp1,
                                             const float* __restrict__ bp1) {
    int warp = (blockIdx.x * 256 + threadIdx.x) >> 5;  // 512 warps
    int lane = threadIdx.x & 31;
    const float4* w = (const float4*)(Wp1 + (size_t)warp * DIM);
    const float4* v = (const float4*)g_x1;
    float a = 0.f;
    for (int it = lane; it < DIM / 4; it += 32) {
        float4 wv = w[it], vv = v[it];
        a += wv.x * vv.x + wv.y * vv.y + wv.z * vv.z + wv.w * vv.w;
    }
    #pragma unroll
    for (int o = 16; o > 0; o >>= 1) a += __shfl_xor_sync(0xffffffffu, a, o);
    if (lane == 0) g_h1[warp] = a + bp1[warp];
}

// ---- k67: LN(h1)+relu (redundant per block) then add = W_p2 @ r + b_p2 ------
__global__ void __launch_bounds__(256) k67_lnp2(const float* __restrict__ Wp2,
                                                const float* __restrict__ bp2,
                                                const float* __restrict__ lnw,
                                                const float* __restrict__ lnb) {
    __shared__ __align__(16) float r_s[PDIM];
    __shared__ float red[256];
    int tid = threadIdx.x;
    float2 v2 = *(const float2*)(g_h1 + tid * 2);
    red[tid] = v2.x + v2.y; __syncthreads();
    for (int o = 128; o > 0; o >>= 1) {
        if (tid < o) red[tid] += red[tid + o];
        __syncthreads();
    }
    float mu = red[0] * (1.f / PDIM);
    __syncthreads();
    float dx = v2.x - mu, dy = v2.y - mu;
    red[tid] = dx * dx + dy * dy; __syncthreads();
    for (int o = 128; o > 0; o >>= 1) {
        if (tid < o) red[tid] += red[tid + o];
        __syncthreads();
    }
    float rstd = rsqrtf(red[0] * (1.f / PDIM) + EPSF);
    float2 w2 = *(const float2*)(lnw + tid * 2);
    float2 b2 = *(const float2*)(lnb + tid * 2);
    r_s[2 * tid]     = fmaxf(dx * rstd * w2.x + b2.x, 0.f);
    r_s[2 * tid + 1] = fmaxf(dy * rstd * w2.y + b2.y, 0.f);
    __syncthreads();
    int wid = tid >> 5, lane = tid & 31;
    #pragma unroll
    for (int k = 0; k < 4; ++k) {
        int row = blockIdx.x * 32 + wid * 4 + k;
        const float4* w = (const float4*)(Wp2 + (size_t)row * PDIM);
        float a = 0.f;
        #pragma unroll
        for (int it = lane; it < PDIM / 4; it += 32) {
            float4 wv = w[it];
            float4 rv = *(const float4*)(r_s + it * 4);
            a += wv.x * rv.x + wv.y * rv.y + wv.z * rv.z + wv.w * rv.w;
        }
        #pragma unroll
        for (int o = 16; o > 0; o >>= 1) a += __shfl_xor_sync(0xffffffffu, a, o);
        if (lane == 0) g_add[row] = a + bp2[row];
    }
}

// ---- k8: out = x + broadcast(add) -------------------------------------------
__global__ void __launch_bounds__(256) k8_resid(const float* __restrict__ x,
                                                float* __restrict__ out) {
    size_t i = (size_t)blockIdx.x * 256 + threadIdx.x;
    const float4* x4 = (const float4*)x;
    const float4* a4 = (const float4*)g_add;
    float4 xv = x4[i];
    float4 av = a4[i & (DIM / 4 - 1)];
    float4 o;
    o.x = xv.x + av.x; o.y = xv.y + av.y; o.z = xv.z + av.z; o.w = xv.w + av.w;
    ((float4*)out)[i] = o;
}

extern "C" void kernel_launch(void* const* d_in, const int* in_sizes, int n_in,
                              void* d_out, int out_size) {
    const float* x    = (const float*)d_in[0];
    const float* q    = (const float*)d_in[1];
    const float* Wkv  = (const float*)d_in[2];
    const float* bkv  = (const float*)d_in[3];
    const float* Wp1  = (const float*)d_in[4];
    const float* bp1  = (const float*)d_in[5];
    const float* Wp2  = (const float*)d_in[6];
    const float* bp2  = (const float*)d_in[7];
    const float* lnw  = (const float*)d_in[8];
    const float* lnb  = (const float*)d_in[9];
    float* out = (float*)d_out;

    static bool attr_set = false;
    if (!attr_set) {
        cudaFuncSetAttribute(k1_logits,
                             cudaFuncAttributeMaxDynamicSharedMemorySize, 208896);
        attr_set = true;
    }

    k0_wq<<<64, 256>>>(q, Wkv);
    k1_logits<<<K1_BLOCKS, 256, 208896>>>(x);
    k3_yaccum<<<NCH3 * 4, 256>>>(x);
    k3b_reduce<<<(H * DIM) / 256, 256>>>();
    k4_x1<<<DIM / 8, 256>>>(Wkv, bkv);
    k5_p1<<<PDIM / 8, 256>>>(Wp1, bp1);
    k67_lnp2<<<DIM / 32, 256>>>(Wp2, bp2, lnw, lnb);
    k8_resid<<<(SEQ * DIM / 4) / 256, 256>>>(x, out);
}